// round 2
// baseline (speedup 1.0000x reference)
#include <cuda_runtime.h>
#include <cstdint>

#define N_INST 300000
#define N_NET  100000
#define NTOT   400000
#define EMB    128

// ---------------- device scratch (module-load allocated, allowed) ----------------
__device__ float g_h0 [(size_t)NTOT * EMB];   // initial embedding (residual source)
__device__ float g_h  [(size_t)NTOT * EMB];   // current layer output
__device__ float g_hm [(size_t)NTOT * EMB];   // mid (after conv, before reconv)
__device__ float g_x  [(size_t)NTOT * EMB];   // post-linear x per conv
__device__ float g_agg[(size_t)NTOT * EMB];   // scatter accumulator
__device__ float g_sc [(size_t)N_INST * 256]; // encoder hidden scratch
__device__ float g_deg1[NTOT], g_dinv1[NTOT];
__device__ float g_deg2[NTOT], g_dinv2[NTOT];

// ---------------- GEMM: C[M,N] = A[M,K] @ W[N,K]^T + b  (optional leaky) ---------
// 64x64 tile, BK=32, 256 threads, 4x4 per-thread micro-tile.
// Smem stored transposed [k][m] so inner-loop reads are conflict-free LDS.128.
template<bool LEAKY>
__global__ void __launch_bounds__(256)
gemm_nt(const float* __restrict__ A, const float* __restrict__ W,
        const float* __restrict__ bias, float* __restrict__ C,
        int M, int N, int K)
{
    __shared__ float As[32][64];
    __shared__ float Ws[32][64];
    const int tid = threadIdx.x;
    const int tx = tid & 15, ty = tid >> 4;
    const int row0 = blockIdx.y << 6, col0 = blockIdx.x << 6;

    float acc[4][4];
#pragma unroll
    for (int i = 0; i < 4; i++)
#pragma unroll
        for (int j = 0; j < 4; j++) acc[i][j] = 0.f;

    for (int k0 = 0; k0 < K; k0 += 32) {
#pragma unroll
        for (int i = 0; i < 2; i++) {
            int s  = tid + (i << 8);      // 0..511 float4 slots
            int m  = s >> 3;              // 0..63
            int kq = (s & 7) << 2;        // 0,4,..,28
            int row = row0 + m;
            float4 va = make_float4(0.f, 0.f, 0.f, 0.f);
            if (row < M) va = *(const float4*)(A + (size_t)row * K + k0 + kq);
            As[kq + 0][m] = va.x; As[kq + 1][m] = va.y;
            As[kq + 2][m] = va.z; As[kq + 3][m] = va.w;
            float4 vw = *(const float4*)(W + (size_t)(col0 + m) * K + k0 + kq);
            Ws[kq + 0][m] = vw.x; Ws[kq + 1][m] = vw.y;
            Ws[kq + 2][m] = vw.z; Ws[kq + 3][m] = vw.w;
        }
        __syncthreads();
#pragma unroll
        for (int kk = 0; kk < 32; kk++) {
            float4 av = *(const float4*)&As[kk][ty << 2];
            float4 wv = *(const float4*)&Ws[kk][tx << 2];
            float a[4] = {av.x, av.y, av.z, av.w};
            float w[4] = {wv.x, wv.y, wv.z, wv.w};
#pragma unroll
            for (int i = 0; i < 4; i++)
#pragma unroll
                for (int j = 0; j < 4; j++) acc[i][j] += a[i] * w[j];
        }
        __syncthreads();
    }

    float4 bv = *(const float4*)(bias + col0 + (tx << 2));
    float bb[4] = {bv.x, bv.y, bv.z, bv.w};
#pragma unroll
    for (int i = 0; i < 4; i++) {
        int row = row0 + (ty << 2) + i;
        if (row < M) {
            float v[4];
#pragma unroll
            for (int j = 0; j < 4; j++) {
                float t = acc[i][j] + bb[j];
                if (LEAKY) t = (t > 0.f) ? t : 0.1f * t;
                v[j] = t;
            }
            *(float4*)(C + (size_t)row * N + col0 + (tx << 2)) =
                make_float4(v[0], v[1], v[2], v[3]);
        }
    }
}

// ---------------- degree / misc elementwise ----------------
__global__ void fill1_k(float* p, int n) {
    int i = blockIdx.x * blockDim.x + threadIdx.x;
    if (i < n) p[i] = 1.0f;
}
__global__ void deg_count_k(const int* __restrict__ row, float* deg, int E) {
    int i = blockIdx.x * blockDim.x + threadIdx.x;
    if (i < E) atomicAdd(deg + __ldg(row + i), 1.0f);
}
__global__ void dinv_k(const float* __restrict__ deg, float* dinv, int n) {
    int i = blockIdx.x * blockDim.x + threadIdx.x;
    if (i < n) dinv[i] = rsqrtf(deg[i]);
}

// ---------------- edge scatter: one warp per edge ----------------
// agg[col] += dinv[row]*dinv[col] * relu(x[row]), 128 floats via 32 lanes x float4
__global__ void edge_scatter_k(const int* __restrict__ row, const int* __restrict__ col,
                               const float* __restrict__ dinv, const float* __restrict__ x,
                               float* __restrict__ agg, int E)
{
    int w = (blockIdx.x * blockDim.x + threadIdx.x) >> 5;
    if (w >= E) return;
    int lane = threadIdx.x & 31;
    int r = __ldg(row + w);
    int c = __ldg(col + w);
    float s = __ldg(dinv + r) * __ldg(dinv + c);
    float4 v = __ldg((const float4*)(x + (size_t)r * EMB) + lane);
    float mx = fmaxf(v.x, 0.f) * s;
    float my = fmaxf(v.y, 0.f) * s;
    float mz = fmaxf(v.z, 0.f) * s;
    float mw = fmaxf(v.w, 0.f) * s;
    float* dst = agg + (size_t)c * EMB + (lane << 2);
    asm volatile("red.global.add.v4.f32 [%0], {%1, %2, %3, %4};"
                 :: "l"(dst), "f"(mx), "f"(my), "f"(mz), "f"(mw) : "memory");
}

// ---------------- finalize after conv (mid-layer): h = agg + relu(x+root)/deg ----
__global__ void finalize_mid_k(const float* __restrict__ agg, const float* __restrict__ x,
                               const float* __restrict__ root, const float* __restrict__ deg,
                               float* __restrict__ out)
{
    int idx = blockIdx.x * blockDim.x + threadIdx.x;   // float4 index
    if (idx >= NTOT * 32) return;
    int node = idx >> 5, q = idx & 31;
    float4 a = ((const float4*)agg)[idx];
    float4 v = ((const float4*)x)[idx];
    float4 r = ((const float4*)root)[q];
    float invd = 1.0f / __ldg(deg + node);
    float4 o;
    o.x = a.x + fmaxf(v.x + r.x, 0.f) * invd;
    o.y = a.y + fmaxf(v.y + r.y, 0.f) * invd;
    o.z = a.z + fmaxf(v.z + r.z, 0.f) * invd;
    o.w = a.w + fmaxf(v.w + r.w, 0.f) * invd;
    ((float4*)out)[idx] = o;
}

// ---------------- finalize after reconv (layer end): residual + LN + leaky + out --
// one warp per node; lane handles 4 features (float4)
__global__ void finalize_end_k(const float* __restrict__ agg, const float* __restrict__ x,
                               const float* __restrict__ root, const float* __restrict__ deg,
                               const float* __restrict__ h0,
                               const float* __restrict__ lng, const float* __restrict__ lnb,
                               float* __restrict__ hout, float* __restrict__ out, int layer)
{
    int node = (blockIdx.x * blockDim.x + threadIdx.x) >> 5;
    if (node >= NTOT) return;
    int lane = threadIdx.x & 31;
    size_t off = (size_t)node * 32 + lane;   // float4 index
    float4 a = ((const float4*)agg)[off];
    float4 v = ((const float4*)x)[off];
    float4 r = ((const float4*)root)[lane];
    float4 h = ((const float4*)h0)[off];
    float invd = 1.0f / __ldg(deg + node);
    float4 t;
    t.x = a.x + fmaxf(v.x + r.x, 0.f) * invd + h.x;
    t.y = a.y + fmaxf(v.y + r.y, 0.f) * invd + h.y;
    t.z = a.z + fmaxf(v.z + r.z, 0.f) * invd + h.z;
    t.w = a.w + fmaxf(v.w + r.w, 0.f) * invd + h.w;

    float s  = t.x + t.y + t.z + t.w;
    float ss = t.x * t.x + t.y * t.y + t.z * t.z + t.w * t.w;
#pragma unroll
    for (int o = 16; o; o >>= 1) {
        s  += __shfl_xor_sync(0xffffffffu, s, o);
        ss += __shfl_xor_sync(0xffffffffu, ss, o);
    }
    float mean = s * (1.0f / 128.0f);
    float var  = ss * (1.0f / 128.0f) - mean * mean;
    float rstd = rsqrtf(var + 1e-5f);
    float4 g = ((const float4*)lng)[lane];
    float4 b = ((const float4*)lnb)[lane];
    float4 y;
    y.x = (t.x - mean) * rstd * g.x + b.x;
    y.y = (t.y - mean) * rstd * g.y + b.y;
    y.z = (t.z - mean) * rstd * g.z + b.z;
    y.w = (t.w - mean) * rstd * g.w + b.w;
    y.x = (y.x > 0.f) ? y.x : 0.1f * y.x;
    y.y = (y.y > 0.f) ? y.y : 0.1f * y.y;
    y.z = (y.z > 0.f) ? y.z : 0.1f * y.z;
    y.w = (y.w > 0.f) ? y.w : 0.1f * y.w;
    ((float4*)hout)[off] = y;
    if (node >= N_INST) {
        size_t oo = (size_t)(node - N_INST) * 128 + (size_t)(layer + 1) * 32 + lane;
        ((float4*)out)[oo] = y;
    }
}

// ---------------- write out[:, 0:128] = h0[net nodes] ----------------
__global__ void copy_out0_k(const float* __restrict__ h0, float* __restrict__ out)
{
    int idx = blockIdx.x * blockDim.x + threadIdx.x;   // float4 index over net rows
    if (idx >= N_NET * 32) return;
    int n = idx >> 5, q = idx & 31;
    ((float4*)out)[(size_t)n * 128 + q] =
        ((const float4*)h0)[(size_t)(N_INST + n) * 32 + q];
}

// ---------------- launch ----------------
extern "C" void kernel_launch(void* const* d_in, const int* in_sizes, int n_in,
                              void* d_out, int out_size)
{
    const float* x       = (const float*)d_in[0];
    const float* x_net   = (const float*)d_in[1];
    const int*   ei1     = (const int*)d_in[2];
    const int*   ei2     = (const int*)d_in[3];
    const float* enc1_W  = (const float*)d_in[5];
    const float* enc1_b  = (const float*)d_in[6];
    const float* enc2_W  = (const float*)d_in[7];
    const float* enc2_b  = (const float*)d_in[8];
    const float* encn1_W = (const float*)d_in[9];
    const float* encn1_b = (const float*)d_in[10];
    const float* encn2_W = (const float*)d_in[11];
    const float* encn2_b = (const float*)d_in[12];
    const float* conv_W  = (const float*)d_in[13];
    const float* conv_b  = (const float*)d_in[14];
    const float* conv_r  = (const float*)d_in[15];
    const float* rec_W   = (const float*)d_in[16];
    const float* rec_b   = (const float*)d_in[17];
    const float* rec_r   = (const float*)d_in[18];
    const float* ln_g    = (const float*)d_in[19];
    const float* ln_b    = (const float*)d_in[20];
    float* out = (float*)d_out;
    const int E = in_sizes[2] / 2;

    float *h0, *h, *hm, *xb, *ag, *sc, *deg1, *dinv1, *deg2, *dinv2;
    cudaGetSymbolAddress((void**)&h0,   g_h0);
    cudaGetSymbolAddress((void**)&h,    g_h);
    cudaGetSymbolAddress((void**)&hm,   g_hm);
    cudaGetSymbolAddress((void**)&xb,   g_x);
    cudaGetSymbolAddress((void**)&ag,   g_agg);
    cudaGetSymbolAddress((void**)&sc,   g_sc);
    cudaGetSymbolAddress((void**)&deg1, g_deg1);
    cudaGetSymbolAddress((void**)&dinv1, g_dinv1);
    cudaGetSymbolAddress((void**)&deg2, g_deg2);
    cudaGetSymbolAddress((void**)&dinv2, g_dinv2);

    dim3 blk(256);
    auto gg = [](int M, int N) { return dim3((unsigned)(N / 64), (unsigned)((M + 63) / 64)); };

    // encoders -> h0 (leaky at every linear)
    gemm_nt<true><<<gg(N_INST, 256), blk>>>(x,      enc1_W,  enc1_b,  sc,  N_INST, 256, 64);
    gemm_nt<true><<<gg(N_INST, 128), blk>>>(sc,     enc2_W,  enc2_b,  h0,  N_INST, 128, 256);
    gemm_nt<true><<<gg(N_NET, 128),  blk>>>(x_net,  encn1_W, encn1_b, sc,  N_NET,  128, 64);
    gemm_nt<true><<<gg(N_NET, 128),  blk>>>(sc,     encn2_W, encn2_b, h0 + (size_t)N_INST * EMB,
                                            N_NET, 128, 128);
    copy_out0_k<<<(N_NET * 32 + 255) / 256, blk>>>(h0, out);

    // degrees (per edge set, reused for all layers)
    fill1_k<<<(NTOT + 255) / 256, blk>>>(deg1, NTOT);
    fill1_k<<<(NTOT + 255) / 256, blk>>>(deg2, NTOT);
    deg_count_k<<<(E + 255) / 256, blk>>>(ei1, deg1, E);
    deg_count_k<<<(E + 255) / 256, blk>>>(ei2, deg2, E);
    dinv_k<<<(NTOT + 255) / 256, blk>>>(deg1, dinv1, NTOT);
    dinv_k<<<(NTOT + 255) / 256, blk>>>(deg2, dinv2, NTOT);

    const size_t hbytes = (size_t)NTOT * EMB * sizeof(float);
    const int edge_blocks = (E * 32 + 255) / 256;

    const float* hin = h0;
    for (int l = 0; l < 3; l++) {
        // conv (edge set 1)
        gemm_nt<false><<<gg(NTOT, 128), blk>>>(hin, conv_W + (size_t)l * EMB * EMB,
                                               conv_b + l * EMB, xb, NTOT, 128, 128);
        cudaMemsetAsync(ag, 0, hbytes, 0);
        edge_scatter_k<<<edge_blocks, blk>>>(ei1, ei1 + E, dinv1, xb, ag, E);
        finalize_mid_k<<<(NTOT * 32 + 255) / 256, blk>>>(ag, xb, conv_r + l * EMB, deg1, hm);

        // reconv (edge set 2) + residual + LN + leaky + output write
        gemm_nt<false><<<gg(NTOT, 128), blk>>>(hm, rec_W + (size_t)l * EMB * EMB,
                                               rec_b + l * EMB, xb, NTOT, 128, 128);
        cudaMemsetAsync(ag, 0, hbytes, 0);
        edge_scatter_k<<<edge_blocks, blk>>>(ei2, ei2 + E, dinv2, xb, ag, E);
        finalize_end_k<<<(NTOT * 32 + 255) / 256, blk>>>(ag, xb, rec_r + l * EMB, deg2,
                                                         h0, ln_g + l * EMB, ln_b + l * EMB,
                                                         h, out, l);
        hin = h;
    }
}

// round 4
// speedup vs baseline: 1.3554x; 1.3554x over previous
#include <cuda_runtime.h>
#include <cstdint>

#define N_INST 300000
#define N_NET  100000
#define NTOT   400000
#define EMB    128
#define EMAX   2000000

// ---------------- device scratch (module-load allocated, allowed) ----------------
__device__ float g_h0 [(size_t)NTOT * EMB];   // initial embedding (residual source)
__device__ float g_h  [(size_t)NTOT * EMB];   // current layer output
__device__ float g_hm [(size_t)NTOT * EMB];   // mid (after conv, before reconv)
__device__ float g_x  [(size_t)NTOT * EMB];   // post-linear x per conv
__device__ float g_sc [(size_t)N_INST * 256]; // encoder hidden scratch
__device__ float g_deg1[NTOT], g_dinv1[NTOT];
__device__ float g_deg2[NTOT], g_dinv2[NTOT];
// CSR (built once per launch, reused across the 3 layers)
__device__ int   g_cnt[NTOT];
__device__ int   g_cur[NTOT];
__device__ int   g_part[1024];
__device__ int   g_off1[NTOT + 1], g_off2[NTOT + 1];
__device__ int   g_src1[EMAX],     g_src2[EMAX];
__device__ float g_scl1[EMAX],     g_scl2[EMAX];

// ---------------- GEMM: C[M,N] = A[M,K] @ W[N,K]^T + b  (optional leaky) ---------
template<bool LEAKY>
__global__ void __launch_bounds__(256)
gemm_nt(const float* __restrict__ A, const float* __restrict__ W,
        const float* __restrict__ bias, float* __restrict__ C,
        int M, int N, int K)
{
    __shared__ float As[32][64];
    __shared__ float Ws[32][64];
    const int tid = threadIdx.x;
    const int tx = tid & 15, ty = tid >> 4;
    const int row0 = blockIdx.y << 6, col0 = blockIdx.x << 6;

    float acc[4][4];
#pragma unroll
    for (int i = 0; i < 4; i++)
#pragma unroll
        for (int j = 0; j < 4; j++) acc[i][j] = 0.f;

    for (int k0 = 0; k0 < K; k0 += 32) {
#pragma unroll
        for (int i = 0; i < 2; i++) {
            int s  = tid + (i << 8);
            int m  = s >> 3;
            int kq = (s & 7) << 2;
            int row = row0 + m;
            float4 va = make_float4(0.f, 0.f, 0.f, 0.f);
            if (row < M) va = *(const float4*)(A + (size_t)row * K + k0 + kq);
            As[kq + 0][m] = va.x; As[kq + 1][m] = va.y;
            As[kq + 2][m] = va.z; As[kq + 3][m] = va.w;
            float4 vw = *(const float4*)(W + (size_t)(col0 + m) * K + k0 + kq);
            Ws[kq + 0][m] = vw.x; Ws[kq + 1][m] = vw.y;
            Ws[kq + 2][m] = vw.z; Ws[kq + 3][m] = vw.w;
        }
        __syncthreads();
#pragma unroll
        for (int kk = 0; kk < 32; kk++) {
            float4 av = *(const float4*)&As[kk][ty << 2];
            float4 wv = *(const float4*)&Ws[kk][tx << 2];
            float a[4] = {av.x, av.y, av.z, av.w};
            float w[4] = {wv.x, wv.y, wv.z, wv.w};
#pragma unroll
            for (int i = 0; i < 4; i++)
#pragma unroll
                for (int j = 0; j < 4; j++) acc[i][j] += a[i] * w[j];
        }
        __syncthreads();
    }

    float4 bv = *(const float4*)(bias + col0 + (tx << 2));
    float bb[4] = {bv.x, bv.y, bv.z, bv.w};
#pragma unroll
    for (int i = 0; i < 4; i++) {
        int row = row0 + (ty << 2) + i;
        if (row < M) {
            float v[4];
#pragma unroll
            for (int j = 0; j < 4; j++) {
                float t = acc[i][j] + bb[j];
                if (LEAKY) t = (t > 0.f) ? t : 0.1f * t;
                v[j] = t;
            }
            *(float4*)(C + (size_t)row * N + col0 + (tx << 2)) =
                make_float4(v[0], v[1], v[2], v[3]);
        }
    }
}

// ---------------- degree / misc elementwise ----------------
__global__ void fill1_k(float* p, int n) {
    int i = blockIdx.x * blockDim.x + threadIdx.x;
    if (i < n) p[i] = 1.0f;
}
__global__ void deg_count_k(const int* __restrict__ row, float* deg, int E) {
    int i = blockIdx.x * blockDim.x + threadIdx.x;
    if (i < E) atomicAdd(deg + __ldg(row + i), 1.0f);
}
__global__ void dinv_k(const float* __restrict__ deg, float* dinv, int n) {
    int i = blockIdx.x * blockDim.x + threadIdx.x;
    if (i < n) dinv[i] = rsqrtf(deg[i]);
}

// ---------------- CSR build: histogram -> scan -> fill ----------------
__global__ void hist_k(const int* __restrict__ col, int* cnt, int E) {
    int i = blockIdx.x * blockDim.x + threadIdx.x;
    if (i < E) atomicAdd(cnt + __ldg(col + i), 1);
}
// pass 1: per-1024-chunk sums
__global__ void scan1_k(const int* __restrict__ cnt, int* part, int n) {
    __shared__ int sh[256];
    int base = blockIdx.x << 10;
    int s = 0;
#pragma unroll
    for (int i = 0; i < 4; i++) {
        int idx = base + threadIdx.x + (i << 8);
        if (idx < n) s += cnt[idx];
    }
    sh[threadIdx.x] = s; __syncthreads();
    for (int o = 128; o; o >>= 1) {
        if (threadIdx.x < o) sh[threadIdx.x] += sh[threadIdx.x + o];
        __syncthreads();
    }
    if (threadIdx.x == 0) part[blockIdx.x] = sh[0];
}
// pass 2: exclusive scan of partials (np <= 512), one block of 512
__global__ void scan2_k(int* part, int np) {
    __shared__ int sh[512];
    int v = (threadIdx.x < np) ? part[threadIdx.x] : 0;
    sh[threadIdx.x] = v; __syncthreads();
    for (int o = 1; o < 512; o <<= 1) {
        int t = (threadIdx.x >= o) ? sh[threadIdx.x - o] : 0;
        __syncthreads();
        sh[threadIdx.x] += t;
        __syncthreads();
    }
    if (threadIdx.x < np) part[threadIdx.x] = sh[threadIdx.x] - v;
}
// pass 3: per-chunk exclusive scan + base; also writes off[n]
__global__ void scan3_k(const int* __restrict__ cnt, const int* __restrict__ part,
                        int* off, int* cur, int n) {
    __shared__ int sh[256];
    int base = blockIdx.x << 10;
    int idx0 = base + (threadIdx.x << 2);
    int c[4]; int tsum = 0;
#pragma unroll
    for (int i = 0; i < 4; i++) {
        c[i] = (idx0 + i < n) ? cnt[idx0 + i] : 0;
        tsum += c[i];
    }
    sh[threadIdx.x] = tsum; __syncthreads();
    int incl = tsum;
    for (int o = 1; o < 256; o <<= 1) {
        int t = (threadIdx.x >= o) ? sh[threadIdx.x - o] : 0;
        __syncthreads();
        sh[threadIdx.x] += t;
        __syncthreads();
    }
    incl = sh[threadIdx.x];
    int running = part[blockIdx.x] + incl - tsum;
#pragma unroll
    for (int i = 0; i < 4; i++) {
        int pos = idx0 + i;
        if (pos < n) { off[pos] = running; cur[pos] = running; }
        running += c[i];
    }
    if (idx0 < n && idx0 + 4 >= n) off[n] = running;
}
__global__ void csr_fill_k(const int* __restrict__ row, const int* __restrict__ col,
                           const float* __restrict__ dinv, int* cur,
                           int* __restrict__ src, float* __restrict__ scl, int E) {
    int e = blockIdx.x * blockDim.x + threadIdx.x;
    if (e >= E) return;
    int r = __ldg(row + e), c = __ldg(col + e);
    int p = atomicAdd(cur + c, 1);
    src[p] = r;
    scl[p] = __ldg(dinv + r) * __ldg(dinv + c);
}

// ---------------- fused conv: gather + self-term (+ residual/LN/leaky/out) ------
// one warp per node; lane owns 4 features (float4)
template<bool END>
__global__ void __launch_bounds__(256)
conv_gather_k(const int* __restrict__ off, const int* __restrict__ src,
              const float* __restrict__ scl, const float* __restrict__ x,
              const float* __restrict__ root, const float* __restrict__ deg,
              const float* __restrict__ h0,
              const float* __restrict__ lng, const float* __restrict__ lnb,
              float* __restrict__ hout, float* __restrict__ out, int layer)
{
    int node = (blockIdx.x * blockDim.x + threadIdx.x) >> 5;
    if (node >= NTOT) return;
    int lane = threadIdx.x & 31;
    int s0 = __ldg(off + node), s1 = __ldg(off + node + 1);

    float4 acc = make_float4(0.f, 0.f, 0.f, 0.f);
    int e = s0;
    for (; e + 1 < s1; e += 2) {      // 2-edge unroll -> 2 LDG.128 in flight
        int   r0 = __ldg(src + e),     r1 = __ldg(src + e + 1);
        float c0 = __ldg(scl + e),     c1 = __ldg(scl + e + 1);
        float4 v0 = __ldg((const float4*)(x + (size_t)r0 * EMB) + lane);
        float4 v1 = __ldg((const float4*)(x + (size_t)r1 * EMB) + lane);
        acc.x += c0 * fmaxf(v0.x, 0.f) + c1 * fmaxf(v1.x, 0.f);
        acc.y += c0 * fmaxf(v0.y, 0.f) + c1 * fmaxf(v1.y, 0.f);
        acc.z += c0 * fmaxf(v0.z, 0.f) + c1 * fmaxf(v1.z, 0.f);
        acc.w += c0 * fmaxf(v0.w, 0.f) + c1 * fmaxf(v1.w, 0.f);
    }
    if (e < s1) {
        int   r0 = __ldg(src + e);
        float c0 = __ldg(scl + e);
        float4 v0 = __ldg((const float4*)(x + (size_t)r0 * EMB) + lane);
        acc.x += c0 * fmaxf(v0.x, 0.f);
        acc.y += c0 * fmaxf(v0.y, 0.f);
        acc.z += c0 * fmaxf(v0.z, 0.f);
        acc.w += c0 * fmaxf(v0.w, 0.f);
    }

    size_t offn = (size_t)node * 32 + lane;
    float4 v = ((const float4*)x)[offn];
    float4 r = ((const float4*)root)[lane];
    float invd = 1.0f / __ldg(deg + node);
    float4 t;
    t.x = acc.x + fmaxf(v.x + r.x, 0.f) * invd;
    t.y = acc.y + fmaxf(v.y + r.y, 0.f) * invd;
    t.z = acc.z + fmaxf(v.z + r.z, 0.f) * invd;
    t.w = acc.w + fmaxf(v.w + r.w, 0.f) * invd;

    if (!END) {
        ((float4*)hout)[offn] = t;
        return;
    }

    float4 h = ((const float4*)h0)[offn];
    t.x += h.x; t.y += h.y; t.z += h.z; t.w += h.w;

    float s  = t.x + t.y + t.z + t.w;
    float ss = t.x * t.x + t.y * t.y + t.z * t.z + t.w * t.w;
#pragma unroll
    for (int o = 16; o; o >>= 1) {
        s  += __shfl_xor_sync(0xffffffffu, s, o);
        ss += __shfl_xor_sync(0xffffffffu, ss, o);
    }
    float mean = s * (1.0f / 128.0f);
    float var  = ss * (1.0f / 128.0f) - mean * mean;
    float rstd = rsqrtf(var + 1e-5f);
    float4 g = ((const float4*)lng)[lane];
    float4 b = ((const float4*)lnb)[lane];
    float4 y;
    y.x = (t.x - mean) * rstd * g.x + b.x;
    y.y = (t.y - mean) * rstd * g.y + b.y;
    y.z = (t.z - mean) * rstd * g.z + b.z;
    y.w = (t.w - mean) * rstd * g.w + b.w;
    y.x = (y.x > 0.f) ? y.x : 0.1f * y.x;
    y.y = (y.y > 0.f) ? y.y : 0.1f * y.y;
    y.z = (y.z > 0.f) ? y.z : 0.1f * y.z;
    y.w = (y.w > 0.f) ? y.w : 0.1f * y.w;
    ((float4*)hout)[offn] = y;
    if (node >= N_INST) {
        size_t oo = (size_t)(node - N_INST) * 128 + (size_t)(layer + 1) * 32 + lane;
        ((float4*)out)[oo] = y;
    }
}

// ---------------- write out[:, 0:128] = h0[net nodes] ----------------
__global__ void copy_out0_k(const float* __restrict__ h0, float* __restrict__ out)
{
    int idx = blockIdx.x * blockDim.x + threadIdx.x;
    if (idx >= N_NET * 32) return;
    int n = idx >> 5, q = idx & 31;
    ((float4*)out)[(size_t)n * 128 + q] =
        ((const float4*)h0)[(size_t)(N_INST + n) * 32 + q];
}

// ---------------- launch ----------------
extern "C" void kernel_launch(void* const* d_in, const int* in_sizes, int n_in,
                              void* d_out, int out_size)
{
    const float* x       = (const float*)d_in[0];
    const float* x_net   = (const float*)d_in[1];
    const int*   ei1     = (const int*)d_in[2];
    const int*   ei2     = (const int*)d_in[3];
    const float* enc1_W  = (const float*)d_in[5];
    const float* enc1_b  = (const float*)d_in[6];
    const float* enc2_W  = (const float*)d_in[7];
    const float* enc2_b  = (const float*)d_in[8];
    const float* encn1_W = (const float*)d_in[9];
    const float* encn1_b = (const float*)d_in[10];
    const float* encn2_W = (const float*)d_in[11];
    const float* encn2_b = (const float*)d_in[12];
    const float* conv_W  = (const float*)d_in[13];
    const float* conv_b  = (const float*)d_in[14];
    const float* conv_r  = (const float*)d_in[15];
    const float* rec_W   = (const float*)d_in[16];
    const float* rec_b   = (const float*)d_in[17];
    const float* rec_r   = (const float*)d_in[18];
    const float* ln_g    = (const float*)d_in[19];
    const float* ln_b    = (const float*)d_in[20];
    float* out = (float*)d_out;
    const int E = in_sizes[2] / 2;

    float *h0, *h, *hm, *xb, *sc, *deg1, *dinv1, *deg2, *dinv2;
    float *scl1, *scl2;
    int *cnt, *cur, *part, *off1, *off2, *src1, *src2;
    cudaGetSymbolAddress((void**)&h0,    g_h0);
    cudaGetSymbolAddress((void**)&h,     g_h);
    cudaGetSymbolAddress((void**)&hm,    g_hm);
    cudaGetSymbolAddress((void**)&xb,    g_x);
    cudaGetSymbolAddress((void**)&sc,    g_sc);
    cudaGetSymbolAddress((void**)&deg1,  g_deg1);
    cudaGetSymbolAddress((void**)&dinv1, g_dinv1);
    cudaGetSymbolAddress((void**)&deg2,  g_deg2);
    cudaGetSymbolAddress((void**)&dinv2, g_dinv2);
    cudaGetSymbolAddress((void**)&cnt,   g_cnt);
    cudaGetSymbolAddress((void**)&cur,   g_cur);
    cudaGetSymbolAddress((void**)&part,  g_part);
    cudaGetSymbolAddress((void**)&off1,  g_off1);
    cudaGetSymbolAddress((void**)&off2,  g_off2);
    cudaGetSymbolAddress((void**)&src1,  g_src1);
    cudaGetSymbolAddress((void**)&src2,  g_src2);
    cudaGetSymbolAddress((void**)&scl1,  g_scl1);
    cudaGetSymbolAddress((void**)&scl2,  g_scl2);

    dim3 blk(256);
    auto gg = [](int M, int N) { return dim3((unsigned)(N / 64), (unsigned)((M + 63) / 64)); };
    const int npart = (NTOT + 1023) >> 10;   // 391 <= 512
    const int node_blocks = (NTOT + 255) / 256;
    const int edge_blocks = (E + 255) / 256;
    const int warp_blocks = (NTOT * 32 + 255) / 256;

    // encoders -> h0 (leaky at every linear)
    gemm_nt<true><<<gg(N_INST, 256), blk>>>(x,      enc1_W,  enc1_b,  sc,  N_INST, 256, 64);
    gemm_nt<true><<<gg(N_INST, 128), blk>>>(sc,     enc2_W,  enc2_b,  h0,  N_INST, 128, 256);
    gemm_nt<true><<<gg(N_NET, 128),  blk>>>(x_net,  encn1_W, encn1_b, sc,  N_NET,  128, 64);
    gemm_nt<true><<<gg(N_NET, 128),  blk>>>(sc,     encn2_W, encn2_b, h0 + (size_t)N_INST * EMB,
                                            N_NET, 128, 128);
    copy_out0_k<<<(N_NET * 32 + 255) / 256, blk>>>(h0, out);

    // degrees (row-side, matches reference: deg = segment_sum(ones,row)+1)
    fill1_k<<<node_blocks, blk>>>(deg1, NTOT);
    fill1_k<<<node_blocks, blk>>>(deg2, NTOT);
    deg_count_k<<<edge_blocks, blk>>>(ei1, deg1, E);
    deg_count_k<<<edge_blocks, blk>>>(ei2, deg2, E);
    dinv_k<<<node_blocks, blk>>>(deg1, dinv1, NTOT);
    dinv_k<<<node_blocks, blk>>>(deg2, dinv2, NTOT);

    // CSR build, edge set 1 (by destination col)
    cudaMemsetAsync(cnt, 0, NTOT * sizeof(int), 0);
    hist_k<<<edge_blocks, blk>>>(ei1 + E, cnt, E);
    scan1_k<<<npart, blk>>>(cnt, part, NTOT);
    scan2_k<<<1, 512>>>(part, npart);
    scan3_k<<<npart, blk>>>(cnt, part, off1, cur, NTOT);
    csr_fill_k<<<edge_blocks, blk>>>(ei1, ei1 + E, dinv1, cur, src1, scl1, E);

    // CSR build, edge set 2
    cudaMemsetAsync(cnt, 0, NTOT * sizeof(int), 0);
    hist_k<<<edge_blocks, blk>>>(ei2 + E, cnt, E);
    scan1_k<<<npart, blk>>>(cnt, part, NTOT);
    scan2_k<<<1, 512>>>(part, npart);
    scan3_k<<<npart, blk>>>(cnt, part, off2, cur, NTOT);
    csr_fill_k<<<edge_blocks, blk>>>(ei2, ei2 + E, dinv2, cur, src2, scl2, E);

    const float* hin = h0;
    for (int l = 0; l < 3; l++) {
        // conv (edge set 1) -> hm
        gemm_nt<false><<<gg(NTOT, 128), blk>>>(hin, conv_W + (size_t)l * EMB * EMB,
                                               conv_b + l * EMB, xb, NTOT, 128, 128);
        conv_gather_k<false><<<warp_blocks, blk>>>(off1, src1, scl1, xb,
                                                   conv_r + l * EMB, deg1,
                                                   nullptr, nullptr, nullptr,
                                                   hm, nullptr, l);
        // reconv (edge set 2) + residual + LN + leaky + output write -> h
        gemm_nt<false><<<gg(NTOT, 128), blk>>>(hm, rec_W + (size_t)l * EMB * EMB,
                                               rec_b + l * EMB, xb, NTOT, 128, 128);
        conv_gather_k<true><<<warp_blocks, blk>>>(off2, src2, scl2, xb,
                                                  rec_r + l * EMB, deg2,
                                                  h0, ln_g + l * EMB, ln_b + l * EMB,
                                                  h, out, l);
        hin = h;
    }
}

// round 7
// speedup vs baseline: 1.8488x; 1.3640x over previous
#include <cuda_runtime.h>
#include <cstdint>

#define N_INST 300000
#define N_NET  100000
#define NTOT   400000
#define EMB    128
#define EMAX   2000000

// ---------------- device scratch (module-load allocated, allowed) ----------------
__device__ float g_h0 [(size_t)NTOT * EMB];   // initial embedding (residual source)
__device__ float g_h  [(size_t)NTOT * EMB];   // current layer output
__device__ float g_hm [(size_t)NTOT * EMB];   // mid (after conv, before reconv)
__device__ float g_x  [(size_t)NTOT * EMB];   // post-linear x per conv
__device__ float g_sc [(size_t)N_INST * 256]; // encoder hidden scratch
__device__ float g_deg1[NTOT], g_dinv1[NTOT];
__device__ float g_deg2[NTOT], g_dinv2[NTOT];
// CSR (built once per launch, reused across the 3 layers)
__device__ int   g_cnt[NTOT];
__device__ int   g_cur[NTOT];
__device__ int   g_part[1024];
__device__ int   g_off1[NTOT + 1], g_off2[NTOT + 1];
__device__ int   g_src1[EMAX],     g_src2[EMAX];
__device__ float g_scl1[EMAX],     g_scl2[EMAX];

// ---------------- GEMM: C[M,N] = A[M,K] @ W[N,K]^T + b  (optional leaky) ---------
// 128x128 tile, BK=8, 256 threads, 8x8 per-thread micro-tile (split 4+4 fragments).
// 64 FMA per 4 LDS.128 per k-step -> FMA-bound. Register-prefetched global loads.
template<bool LEAKY>
__global__ void __launch_bounds__(256)
gemm128(const float* __restrict__ A, const float* __restrict__ W,
        const float* __restrict__ bias, float* __restrict__ C,
        int M, int N, int K)
{
    __shared__ float As[8][128];
    __shared__ float Ws[8][128];
    const int tid = threadIdx.x;
    const int tx = tid & 15, ty = tid >> 4;          // 16 x 16 threads
    const int row0 = blockIdx.x << 7;                // M block
    const int col0 = blockIdx.y << 7;                // N block

    const int lr = tid >> 1;                         // 0..127 (tile row)
    const int lk = (tid & 1) << 2;                   // 0 or 4 (k quad)

    float acc[8][8];
#pragma unroll
    for (int i = 0; i < 8; i++)
#pragma unroll
        for (int j = 0; j < 8; j++) acc[i][j] = 0.f;

    const int  arow = row0 + lr;
    const bool avalid = (arow < M);
    const float* aptr = A + (size_t)arow * K + lk;
    const float* wptr = W + (size_t)(col0 + lr) * K + lk;

    float4 va = avalid ? *(const float4*)aptr : make_float4(0.f, 0.f, 0.f, 0.f);
    float4 vw = *(const float4*)wptr;

    for (int k0 = 0; ; ) {
        As[lk + 0][lr] = va.x; As[lk + 1][lr] = va.y;
        As[lk + 2][lr] = va.z; As[lk + 3][lr] = va.w;
        Ws[lk + 0][lr] = vw.x; Ws[lk + 1][lr] = vw.y;
        Ws[lk + 2][lr] = vw.z; Ws[lk + 3][lr] = vw.w;
        __syncthreads();

        k0 += 8;
        const bool more = (k0 < K);
        if (more) {
            va = avalid ? *(const float4*)(aptr + k0) : make_float4(0.f, 0.f, 0.f, 0.f);
            vw = *(const float4*)(wptr + k0);
        }

#pragma unroll
        for (int kk = 0; kk < 8; kk++) {
            float4 a0 = *(const float4*)&As[kk][ty << 2];
            float4 a1 = *(const float4*)&As[kk][64 + (ty << 2)];
            float4 b0 = *(const float4*)&Ws[kk][tx << 2];
            float4 b1 = *(const float4*)&Ws[kk][64 + (tx << 2)];
            float am[8] = {a0.x, a0.y, a0.z, a0.w, a1.x, a1.y, a1.z, a1.w};
            float bn[8] = {b0.x, b0.y, b0.z, b0.w, b1.x, b1.y, b1.z, b1.w};
#pragma unroll
            for (int i = 0; i < 8; i++)
#pragma unroll
                for (int j = 0; j < 8; j++) acc[i][j] += am[i] * bn[j];
        }
        __syncthreads();
        if (!more) break;
    }

    float4 bv0 = *(const float4*)(bias + col0 + (tx << 2));
    float4 bv1 = *(const float4*)(bias + col0 + 64 + (tx << 2));
    float bb[8] = {bv0.x, bv0.y, bv0.z, bv0.w, bv1.x, bv1.y, bv1.z, bv1.w};

#pragma unroll
    for (int i = 0; i < 8; i++) {
        int row = row0 + ((i < 4) ? ((ty << 2) + i) : (64 + (ty << 2) + i - 4));
        if (row < M) {
            float v[8];
#pragma unroll
            for (int j = 0; j < 8; j++) {
                float t = acc[i][j] + bb[j];
                if (LEAKY) t = (t > 0.f) ? t : 0.1f * t;
                v[j] = t;
            }
            *(float4*)(C + (size_t)row * N + col0 + (tx << 2)) =
                make_float4(v[0], v[1], v[2], v[3]);
            *(float4*)(C + (size_t)row * N + col0 + 64 + (tx << 2)) =
                make_float4(v[4], v[5], v[6], v[7]);
        }
    }
}

// ---------------- degree / misc elementwise ----------------
__global__ void fill1_k(float* p, int n) {
    int i = blockIdx.x * blockDim.x + threadIdx.x;
    if (i < n) p[i] = 1.0f;
}
__global__ void deg_count_k(const int* __restrict__ row, float* deg, int E) {
    int i = blockIdx.x * blockDim.x + threadIdx.x;
    if (i < E) atomicAdd(deg + __ldg(row + i), 1.0f);
}
__global__ void dinv_k(const float* __restrict__ deg, float* dinv, int n) {
    int i = blockIdx.x * blockDim.x + threadIdx.x;
    if (i < n) dinv[i] = rsqrtf(deg[i]);
}

// ---------------- CSR build: histogram -> scan -> fill ----------------
__global__ void hist_k(const int* __restrict__ col, int* cnt, int E) {
    int i = blockIdx.x * blockDim.x + threadIdx.x;
    if (i < E) atomicAdd(cnt + __ldg(col + i), 1);
}
// pass 1: per-1024-chunk sums
__global__ void scan1_k(const int* __restrict__ cnt, int* part, int n) {
    __shared__ int sh[256];
    int base = blockIdx.x << 10;
    int s = 0;
#pragma unroll
    for (int i = 0; i < 4; i++) {
        int idx = base + threadIdx.x + (i << 8);
        if (idx < n) s += cnt[idx];
    }
    sh[threadIdx.x] = s; __syncthreads();
    for (int o = 128; o; o >>= 1) {
        if (threadIdx.x < o) sh[threadIdx.x] += sh[threadIdx.x + o];
        __syncthreads();
    }
    if (threadIdx.x == 0) part[blockIdx.x] = sh[0];
}
// pass 2: exclusive scan of partials (np <= 512), one block of 512
__global__ void scan2_k(int* part, int np) {
    __shared__ int sh[512];
    int v = (threadIdx.x < np) ? part[threadIdx.x] : 0;
    sh[threadIdx.x] = v; __syncthreads();
    for (int o = 1; o < 512; o <<= 1) {
        int t = (threadIdx.x >= o) ? sh[threadIdx.x - o] : 0;
        __syncthreads();
        sh[threadIdx.x] += t;
        __syncthreads();
    }
    if (threadIdx.x < np) part[threadIdx.x] = sh[threadIdx.x] - v;
}
// pass 3: per-chunk exclusive scan + base; also writes off[n]
__global__ void scan3_k(const int* __restrict__ cnt, const int* __restrict__ part,
                        int* off, int* cur, int n) {
    __shared__ int sh[256];
    int base = blockIdx.x << 10;
    int idx0 = base + (threadIdx.x << 2);
    int c[4]; int tsum = 0;
#pragma unroll
    for (int i = 0; i < 4; i++) {
        c[i] = (idx0 + i < n) ? cnt[idx0 + i] : 0;
        tsum += c[i];
    }
    sh[threadIdx.x] = tsum; __syncthreads();
    int incl = tsum;
    for (int o = 1; o < 256; o <<= 1) {
        int t = (threadIdx.x >= o) ? sh[threadIdx.x - o] : 0;
        __syncthreads();
        sh[threadIdx.x] += t;
        __syncthreads();
    }
    incl = sh[threadIdx.x];
    int running = part[blockIdx.x] + incl - tsum;
#pragma unroll
    for (int i = 0; i < 4; i++) {
        int pos = idx0 + i;
        if (pos < n) { off[pos] = running; cur[pos] = running; }
        running += c[i];
    }
    if (idx0 < n && idx0 + 4 >= n) off[n] = running;
}
__global__ void csr_fill_k(const int* __restrict__ row, const int* __restrict__ col,
                           const float* __restrict__ dinv, int* cur,
                           int* __restrict__ src, float* __restrict__ scl, int E) {
    int e = blockIdx.x * blockDim.x + threadIdx.x;
    if (e >= E) return;
    int r = __ldg(row + e), c = __ldg(col + e);
    int p = atomicAdd(cur + c, 1);
    src[p] = r;
    scl[p] = __ldg(dinv + r) * __ldg(dinv + c);
}

// ---------------- fused conv: gather + self-term (+ residual/LN/leaky/out) ------
// one warp per node; lane owns 4 features (float4)
template<bool END>
__global__ void __launch_bounds__(256)
conv_gather_k(const int* __restrict__ off, const int* __restrict__ src,
              const float* __restrict__ scl, const float* __restrict__ x,
              const float* __restrict__ root, const float* __restrict__ deg,
              const float* __restrict__ h0,
              const float* __restrict__ lng, const float* __restrict__ lnb,
              float* __restrict__ hout, float* __restrict__ out, int layer)
{
    int node = (blockIdx.x * blockDim.x + threadIdx.x) >> 5;
    if (node >= NTOT) return;
    int lane = threadIdx.x & 31;
    int s0 = __ldg(off + node), s1 = __ldg(off + node + 1);

    float4 acc = make_float4(0.f, 0.f, 0.f, 0.f);
    int e = s0;
    for (; e + 1 < s1; e += 2) {      // 2-edge unroll -> 2 LDG.128 in flight
        int   r0 = __ldg(src + e),     r1 = __ldg(src + e + 1);
        float c0 = __ldg(scl + e),     c1 = __ldg(scl + e + 1);
        float4 v0 = __ldg((const float4*)(x + (size_t)r0 * EMB) + lane);
        float4 v1 = __ldg((const float4*)(x + (size_t)r1 * EMB) + lane);
        acc.x += c0 * fmaxf(v0.x, 0.f) + c1 * fmaxf(v1.x, 0.f);
        acc.y += c0 * fmaxf(v0.y, 0.f) + c1 * fmaxf(v1.y, 0.f);
        acc.z += c0 * fmaxf(v0.z, 0.f) + c1 * fmaxf(v1.z, 0.f);
        acc.w += c0 * fmaxf(v0.w, 0.f) + c1 * fmaxf(v1.w, 0.f);
    }
    if (e < s1) {
        int   r0 = __ldg(src + e);
        float c0 = __ldg(scl + e);
        float4 v0 = __ldg((const float4*)(x + (size_t)r0 * EMB) + lane);
        acc.x += c0 * fmaxf(v0.x, 0.f);
        acc.y += c0 * fmaxf(v0.y, 0.f);
        acc.z += c0 * fmaxf(v0.z, 0.f);
        acc.w += c0 * fmaxf(v0.w, 0.f);
    }

    size_t offn = (size_t)node * 32 + lane;
    float4 v = ((const float4*)x)[offn];
    float4 r = ((const float4*)root)[lane];
    float invd = 1.0f / __ldg(deg + node);
    float4 t;
    t.x = acc.x + fmaxf(v.x + r.x, 0.f) * invd;
    t.y = acc.y + fmaxf(v.y + r.y, 0.f) * invd;
    t.z = acc.z + fmaxf(v.z + r.z, 0.f) * invd;
    t.w = acc.w + fmaxf(v.w + r.w, 0.f) * invd;

    if (!END) {
        ((float4*)hout)[offn] = t;
        return;
    }

    float4 h = ((const float4*)h0)[offn];
    t.x += h.x; t.y += h.y; t.z += h.z; t.w += h.w;

    float s  = t.x + t.y + t.z + t.w;
    float ss = t.x * t.x + t.y * t.y + t.z * t.z + t.w * t.w;
#pragma unroll
    for (int o = 16; o; o >>= 1) {
        s  += __shfl_xor_sync(0xffffffffu, s, o);
        ss += __shfl_xor_sync(0xffffffffu, ss, o);
    }
    float mean = s * (1.0f / 128.0f);
    float var  = ss * (1.0f / 128.0f) - mean * mean;
    float rstd = rsqrtf(var + 1e-5f);
    float4 g = ((const float4*)lng)[lane];
    float4 b = ((const float4*)lnb)[lane];
    float4 y;
    y.x = (t.x - mean) * rstd * g.x + b.x;
    y.y = (t.y - mean) * rstd * g.y + b.y;
    y.z = (t.z - mean) * rstd * g.z + b.z;
    y.w = (t.w - mean) * rstd * g.w + b.w;
    y.x = (y.x > 0.f) ? y.x : 0.1f * y.x;
    y.y = (y.y > 0.f) ? y.y : 0.1f * y.y;
    y.z = (y.z > 0.f) ? y.z : 0.1f * y.z;
    y.w = (y.w > 0.f) ? y.w : 0.1f * y.w;
    ((float4*)hout)[offn] = y;
    if (node >= N_INST) {
        size_t oo = (size_t)(node - N_INST) * 128 + (size_t)(layer + 1) * 32 + lane;
        ((float4*)out)[oo] = y;
    }
}

// ---------------- write out[:, 0:128] = h0[net nodes] ----------------
__global__ void copy_out0_k(const float* __restrict__ h0, float* __restrict__ out)
{
    int idx = blockIdx.x * blockDim.x + threadIdx.x;
    if (idx >= N_NET * 32) return;
    int n = idx >> 5, q = idx & 31;
    ((float4*)out)[(size_t)n * 128 + q] =
        ((const float4*)h0)[(size_t)(N_INST + n) * 32 + q];
}

// ---------------- launch ----------------
extern "C" void kernel_launch(void* const* d_in, const int* in_sizes, int n_in,
                              void* d_out, int out_size)
{
    const float* x       = (const float*)d_in[0];
    const float* x_net   = (const float*)d_in[1];
    const int*   ei1     = (const int*)d_in[2];
    const int*   ei2     = (const int*)d_in[3];
    const float* enc1_W  = (const float*)d_in[5];
    const float* enc1_b  = (const float*)d_in[6];
    const float* enc2_W  = (const float*)d_in[7];
    const float* enc2_b  = (const float*)d_in[8];
    const float* encn1_W = (const float*)d_in[9];
    const float* encn1_b = (const float*)d_in[10];
    const float* encn2_W = (const float*)d_in[11];
    const float* encn2_b = (const float*)d_in[12];
    const float* conv_W  = (const float*)d_in[13];
    const float* conv_b  = (const float*)d_in[14];
    const float* conv_r  = (const float*)d_in[15];
    const float* rec_W   = (const float*)d_in[16];
    const float* rec_b   = (const float*)d_in[17];
    const float* rec_r   = (const float*)d_in[18];
    const float* ln_g    = (const float*)d_in[19];
    const float* ln_b    = (const float*)d_in[20];
    float* out = (float*)d_out;
    const int E = in_sizes[2] / 2;

    float *h0, *h, *hm, *xb, *sc, *deg1, *dinv1, *deg2, *dinv2;
    float *scl1, *scl2;
    int *cnt, *cur, *part, *off1, *off2, *src1, *src2;
    cudaGetSymbolAddress((void**)&h0,    g_h0);
    cudaGetSymbolAddress((void**)&h,     g_h);
    cudaGetSymbolAddress((void**)&hm,    g_hm);
    cudaGetSymbolAddress((void**)&xb,    g_x);
    cudaGetSymbolAddress((void**)&sc,    g_sc);
    cudaGetSymbolAddress((void**)&deg1,  g_deg1);
    cudaGetSymbolAddress((void**)&dinv1, g_dinv1);
    cudaGetSymbolAddress((void**)&deg2,  g_deg2);
    cudaGetSymbolAddress((void**)&dinv2, g_dinv2);
    cudaGetSymbolAddress((void**)&cnt,   g_cnt);
    cudaGetSymbolAddress((void**)&cur,   g_cur);
    cudaGetSymbolAddress((void**)&part,  g_part);
    cudaGetSymbolAddress((void**)&off1,  g_off1);
    cudaGetSymbolAddress((void**)&off2,  g_off2);
    cudaGetSymbolAddress((void**)&src1,  g_src1);
    cudaGetSymbolAddress((void**)&src2,  g_src2);
    cudaGetSymbolAddress((void**)&scl1,  g_scl1);
    cudaGetSymbolAddress((void**)&scl2,  g_scl2);

    dim3 blk(256);
    auto gg = [](int M, int N) { return dim3((unsigned)((M + 127) / 128), (unsigned)(N / 128)); };
    const int npart = (NTOT + 1023) >> 10;   // 391 <= 512
    const int node_blocks = (NTOT + 255) / 256;
    const int edge_blocks = (E + 255) / 256;
    const int warp_blocks = (NTOT * 32 + 255) / 256;

    // encoders -> h0 (leaky at every linear)
    gemm128<true><<<gg(N_INST, 256), blk>>>(x,      enc1_W,  enc1_b,  sc,  N_INST, 256, 64);
    gemm128<true><<<gg(N_INST, 128), blk>>>(sc,     enc2_W,  enc2_b,  h0,  N_INST, 128, 256);
    gemm128<true><<<gg(N_NET, 128),  blk>>>(x_net,  encn1_W, encn1_b, sc,  N_NET,  128, 64);
    gemm128<true><<<gg(N_NET, 128),  blk>>>(sc,     encn2_W, encn2_b, h0 + (size_t)N_INST * EMB,
                                            N_NET, 128, 128);
    copy_out0_k<<<(N_NET * 32 + 255) / 256, blk>>>(h0, out);

    // degrees (row-side, matches reference: deg = segment_sum(ones,row)+1)
    fill1_k<<<node_blocks, blk>>>(deg1, NTOT);
    fill1_k<<<node_blocks, blk>>>(deg2, NTOT);
    deg_count_k<<<edge_blocks, blk>>>(ei1, deg1, E);
    deg_count_k<<<edge_blocks, blk>>>(ei2, deg2, E);
    dinv_k<<<node_blocks, blk>>>(deg1, dinv1, NTOT);
    dinv_k<<<node_blocks, blk>>>(deg2, dinv2, NTOT);

    // CSR build, edge set 1 (by destination col)
    cudaMemsetAsync(cnt, 0, NTOT * sizeof(int), 0);
    hist_k<<<edge_blocks, blk>>>(ei1 + E, cnt, E);
    scan1_k<<<npart, blk>>>(cnt, part, NTOT);
    scan2_k<<<1, 512>>>(part, npart);
    scan3_k<<<npart, blk>>>(cnt, part, off1, cur, NTOT);
    csr_fill_k<<<edge_blocks, blk>>>(ei1, ei1 + E, dinv1, cur, src1, scl1, E);

    // CSR build, edge set 2
    cudaMemsetAsync(cnt, 0, NTOT * sizeof(int), 0);
    hist_k<<<edge_blocks, blk>>>(ei2 + E, cnt, E);
    scan1_k<<<npart, blk>>>(cnt, part, NTOT);
    scan2_k<<<1, 512>>>(part, npart);
    scan3_k<<<npart, blk>>>(cnt, part, off2, cur, NTOT);
    csr_fill_k<<<edge_blocks, blk>>>(ei2, ei2 + E, dinv2, cur, src2, scl2, E);

    const float* hin = h0;
    for (int l = 0; l < 3; l++) {
        // conv (edge set 1) -> hm
        gemm128<false><<<gg(NTOT, 128), blk>>>(hin, conv_W + (size_t)l * EMB * EMB,
                                               conv_b + l * EMB, xb, NTOT, 128, 128);
        conv_gather_k<false><<<warp_blocks, blk>>>(off1, src1, scl1, xb,
                                                   conv_r + l * EMB, deg1,
                                                   nullptr, nullptr, nullptr,
                                                   hm, nullptr, l);
        // reconv (edge set 2) + residual + LN + leaky + output write -> h
        gemm128<false><<<gg(NTOT, 128), blk>>>(hm, rec_W + (size_t)l * EMB * EMB,
                                               rec_b + l * EMB, xb, NTOT, 128, 128);
        conv_gather_k<true><<<warp_blocks, blk>>>(off2, src2, scl2, xb,
                                                  rec_r + l * EMB, deg2,
                                                  h0, ln_g + l * EMB, ln_b + l * EMB,
                                                  h, out, l);
        hin = h;
    }
}

// round 16
// speedup vs baseline: 2.6071x; 1.4102x over previous
#include <cuda_runtime.h>
#include <cstdint>

#define N_INST 300000
#define N_NET  100000
#define NTOT   400000
#define EMB    128
#define EMAX   2000000

// ---------------- device scratch (module-load allocated, allowed) ----------------
__device__ float g_h0 [(size_t)NTOT * EMB];
__device__ float g_h  [(size_t)NTOT * EMB];
__device__ float g_hm [(size_t)NTOT * EMB];
__device__ float g_x  [(size_t)NTOT * EMB];
__device__ float g_sc [(size_t)N_INST * 256];
__device__ float g_deg1[NTOT], g_dinv1[NTOT];
__device__ float g_deg2[NTOT], g_dinv2[NTOT];
__device__ int   g_cnt[NTOT];
__device__ int   g_cur[NTOT];
__device__ int   g_part[1024];
__device__ int   g_off1[NTOT + 1], g_off2[NTOT + 1];
__device__ int   g_src1[EMAX],     g_src2[EMAX];
__device__ float g_scl1[EMAX],     g_scl2[EMAX];

// ---------------- TF32 helpers ----------------
__device__ __forceinline__ uint32_t f2tf32(float x) {
    uint32_t r;
    asm("cvt.rna.tf32.f32 %0, %1;" : "=r"(r) : "f"(x));
    return r;
}
__device__ __forceinline__ void mma_tf32(float* d, const uint32_t* a, const uint32_t* b) {
    asm volatile(
        "mma.sync.aligned.m16n8k8.row.col.f32.tf32.tf32.f32 "
        "{%0,%1,%2,%3}, {%4,%5,%6,%7}, {%8,%9}, {%0,%1,%2,%3};"
        : "+f"(d[0]), "+f"(d[1]), "+f"(d[2]), "+f"(d[3])
        : "r"(a[0]), "r"(a[1]), "r"(a[2]), "r"(a[3]), "r"(b[0]), "r"(b[1]));
}

// ---------------- GEMM: C[M,N] = A[M,K] @ W[N,K]^T + b  (tensor core TF32) ------
// 128x128 tile, BK=16, 256 threads = 8 warps (4m x 2n), warp tile 32x64,
// mma m16n8k8 (2 m-frags x 8 n-frags). Smem stride 132 -> conflict-free frag LDS.
template<bool LEAKY>
__global__ void __launch_bounds__(256)
gemm_tc(const float* __restrict__ A, const float* __restrict__ W,
        const float* __restrict__ bias, float* __restrict__ C,
        int M, int N, int K)
{
    __shared__ uint32_t As[16][132];
    __shared__ uint32_t Ws[16][132];
    const int tid  = threadIdx.x;
    const int lane = tid & 31, warp = tid >> 5;
    const int g  = lane >> 2, tg = lane & 3;
    const int wm = (warp & 3) << 5;          // 0,32,64,96
    const int wn = (warp >> 2) << 6;         // 0,64
    const int row0 = blockIdx.x << 7, col0 = blockIdx.y << 7;

    float acc[2][8][4];
#pragma unroll
    for (int i = 0; i < 2; i++)
#pragma unroll
        for (int j = 0; j < 8; j++)
#pragma unroll
            for (int c = 0; c < 4; c++) acc[i][j][c] = 0.f;

    // global->smem mapping: thread owns rows (arow, arow+64), k-quad aq
    const int arow = tid >> 2;               // 0..63
    const int aq   = (tid & 3) << 2;         // 0,4,8,12
    const bool v0 = (row0 + arow)      < M;
    const bool v1 = (row0 + arow + 64) < M;
    const float* aptr0 = A + (size_t)(row0 + arow) * K + aq;
    const float* aptr1 = aptr0 + (size_t)64 * K;
    const float* wptr0 = W + (size_t)(col0 + arow) * K + aq;
    const float* wptr1 = wptr0 + (size_t)64 * K;

    float4 z = make_float4(0.f, 0.f, 0.f, 0.f);
    float4 va0 = v0 ? *(const float4*)aptr0 : z;
    float4 va1 = v1 ? *(const float4*)aptr1 : z;
    float4 vw0 = *(const float4*)wptr0;
    float4 vw1 = *(const float4*)wptr1;

    for (int k0 = 0;;) {
        As[aq + 0][arow]      = f2tf32(va0.x);
        As[aq + 1][arow]      = f2tf32(va0.y);
        As[aq + 2][arow]      = f2tf32(va0.z);
        As[aq + 3][arow]      = f2tf32(va0.w);
        As[aq + 0][arow + 64] = f2tf32(va1.x);
        As[aq + 1][arow + 64] = f2tf32(va1.y);
        As[aq + 2][arow + 64] = f2tf32(va1.z);
        As[aq + 3][arow + 64] = f2tf32(va1.w);
        Ws[aq + 0][arow]      = f2tf32(vw0.x);
        Ws[aq + 1][arow]      = f2tf32(vw0.y);
        Ws[aq + 2][arow]      = f2tf32(vw0.z);
        Ws[aq + 3][arow]      = f2tf32(vw0.w);
        Ws[aq + 0][arow + 64] = f2tf32(vw1.x);
        Ws[aq + 1][arow + 64] = f2tf32(vw1.y);
        Ws[aq + 2][arow + 64] = f2tf32(vw1.z);
        Ws[aq + 3][arow + 64] = f2tf32(vw1.w);
        __syncthreads();

        k0 += 16;
        const bool more = (k0 < K);
        if (more) {
            va0 = v0 ? *(const float4*)(aptr0 + k0) : z;
            va1 = v1 ? *(const float4*)(aptr1 + k0) : z;
            vw0 = *(const float4*)(wptr0 + k0);
            vw1 = *(const float4*)(wptr1 + k0);
        }

#pragma unroll
        for (int kk = 0; kk < 16; kk += 8) {
            uint32_t af[2][4], bf[8][2];
#pragma unroll
            for (int mi = 0; mi < 2; mi++) {
                int mb = wm + (mi << 4) + g;
                af[mi][0] = As[kk + tg][mb];
                af[mi][1] = As[kk + tg][mb + 8];
                af[mi][2] = As[kk + tg + 4][mb];
                af[mi][3] = As[kk + tg + 4][mb + 8];
            }
#pragma unroll
            for (int j = 0; j < 8; j++) {
                int nb = wn + (j << 3) + g;
                bf[j][0] = Ws[kk + tg][nb];
                bf[j][1] = Ws[kk + tg + 4][nb];
            }
#pragma unroll
            for (int mi = 0; mi < 2; mi++)
#pragma unroll
                for (int j = 0; j < 8; j++)
                    mma_tf32(acc[mi][j], af[mi], bf[j]);
        }
        __syncthreads();
        if (!more) break;
    }

    // epilogue: c0,c1 -> (row g, col tg*2,+1); c2,c3 -> (row g+8)
#pragma unroll
    for (int mi = 0; mi < 2; mi++) {
        int r0 = row0 + wm + (mi << 4) + g;
#pragma unroll
        for (int j = 0; j < 8; j++) {
            int cb = col0 + wn + (j << 3) + (tg << 1);
            float b0 = __ldg(bias + cb), b1 = __ldg(bias + cb + 1);
            if (r0 < M) {
                float t0 = acc[mi][j][0] + b0;
                float t1 = acc[mi][j][1] + b1;
                if (LEAKY) {
                    t0 = (t0 > 0.f) ? t0 : 0.1f * t0;
                    t1 = (t1 > 0.f) ? t1 : 0.1f * t1;
                }
                *(float2*)(C + (size_t)r0 * N + cb) = make_float2(t0, t1);
            }
            if (r0 + 8 < M) {
                float t2 = acc[mi][j][2] + b0;
                float t3 = acc[mi][j][3] + b1;
                if (LEAKY) {
                    t2 = (t2 > 0.f) ? t2 : 0.1f * t2;
                    t3 = (t3 > 0.f) ? t3 : 0.1f * t3;
                }
                *(float2*)(C + (size_t)(r0 + 8) * N + cb) = make_float2(t2, t3);
            }
        }
    }
}

// ---------------- degree / misc elementwise ----------------
__global__ void fill1_k(float* p, int n) {
    int i = blockIdx.x * blockDim.x + threadIdx.x;
    if (i < n) p[i] = 1.0f;
}
__global__ void deg_count_k(const int* __restrict__ row, float* deg, int E) {
    int i = blockIdx.x * blockDim.x + threadIdx.x;
    if (i < E) atomicAdd(deg + __ldg(row + i), 1.0f);
}
__global__ void dinv_k(const float* __restrict__ deg, float* dinv, int n) {
    int i = blockIdx.x * blockDim.x + threadIdx.x;
    if (i < n) dinv[i] = rsqrtf(deg[i]);
}

// ---------------- CSR build: histogram -> scan -> fill ----------------
__global__ void hist_k(const int* __restrict__ col, int* cnt, int E) {
    int i = blockIdx.x * blockDim.x + threadIdx.x;
    if (i < E) atomicAdd(cnt + __ldg(col + i), 1);
}
__global__ void scan1_k(const int* __restrict__ cnt, int* part, int n) {
    __shared__ int sh[256];
    int base = blockIdx.x << 10;
    int s = 0;
#pragma unroll
    for (int i = 0; i < 4; i++) {
        int idx = base + threadIdx.x + (i << 8);
        if (idx < n) s += cnt[idx];
    }
    sh[threadIdx.x] = s; __syncthreads();
    for (int o = 128; o; o >>= 1) {
        if (threadIdx.x < o) sh[threadIdx.x] += sh[threadIdx.x + o];
        __syncthreads();
    }
    if (threadIdx.x == 0) part[blockIdx.x] = sh[0];
}
__global__ void scan2_k(int* part, int np) {
    __shared__ int sh[512];
    int v = (threadIdx.x < np) ? part[threadIdx.x] : 0;
    sh[threadIdx.x] = v; __syncthreads();
    for (int o = 1; o < 512; o <<= 1) {
        int t = (threadIdx.x >= o) ? sh[threadIdx.x - o] : 0;
        __syncthreads();
        sh[threadIdx.x] += t;
        __syncthreads();
    }
    if (threadIdx.x < np) part[threadIdx.x] = sh[threadIdx.x] - v;
}
__global__ void scan3_k(const int* __restrict__ cnt, const int* __restrict__ part,
                        int* off, int* cur, int n) {
    __shared__ int sh[256];
    int base = blockIdx.x << 10;
    int idx0 = base + (threadIdx.x << 2);
    int c[4]; int tsum = 0;
#pragma unroll
    for (int i = 0; i < 4; i++) {
        c[i] = (idx0 + i < n) ? cnt[idx0 + i] : 0;
        tsum += c[i];
    }
    sh[threadIdx.x] = tsum; __syncthreads();
    int incl = tsum;
    for (int o = 1; o < 256; o <<= 1) {
        int t = (threadIdx.x >= o) ? sh[threadIdx.x - o] : 0;
        __syncthreads();
        sh[threadIdx.x] += t;
        __syncthreads();
    }
    incl = sh[threadIdx.x];
    int running = part[blockIdx.x] + incl - tsum;
#pragma unroll
    for (int i = 0; i < 4; i++) {
        int pos = idx0 + i;
        if (pos < n) { off[pos] = running; cur[pos] = running; }
        running += c[i];
    }
    if (idx0 < n && idx0 + 4 >= n) off[n] = running;
}
__global__ void csr_fill_k(const int* __restrict__ row, const int* __restrict__ col,
                           const float* __restrict__ dinv, int* cur,
                           int* __restrict__ src, float* __restrict__ scl, int E) {
    int e = blockIdx.x * blockDim.x + threadIdx.x;
    if (e >= E) return;
    int r = __ldg(row + e), c = __ldg(col + e);
    int p = atomicAdd(cur + c, 1);
    src[p] = r;
    scl[p] = __ldg(dinv + r) * __ldg(dinv + c);
}

// ---------------- fused conv: gather + self-term (+ residual/LN/leaky/out) ------
template<bool END>
__global__ void __launch_bounds__(256)
conv_gather_k(const int* __restrict__ off, const int* __restrict__ src,
              const float* __restrict__ scl, const float* __restrict__ x,
              const float* __restrict__ root, const float* __restrict__ deg,
              const float* __restrict__ h0,
              const float* __restrict__ lng, const float* __restrict__ lnb,
              float* __restrict__ hout, float* __restrict__ out, int layer)
{
    int node = (blockIdx.x * blockDim.x + threadIdx.x) >> 5;
    if (node >= NTOT) return;
    int lane = threadIdx.x & 31;
    int s0 = __ldg(off + node), s1 = __ldg(off + node + 1);

    float4 acc = make_float4(0.f, 0.f, 0.f, 0.f);
    int e = s0;
    for (; e + 1 < s1; e += 2) {
        int   r0 = __ldg(src + e),     r1 = __ldg(src + e + 1);
        float c0 = __ldg(scl + e),     c1 = __ldg(scl + e + 1);
        float4 v0 = __ldg((const float4*)(x + (size_t)r0 * EMB) + lane);
        float4 v1 = __ldg((const float4*)(x + (size_t)r1 * EMB) + lane);
        acc.x += c0 * fmaxf(v0.x, 0.f) + c1 * fmaxf(v1.x, 0.f);
        acc.y += c0 * fmaxf(v0.y, 0.f) + c1 * fmaxf(v1.y, 0.f);
        acc.z += c0 * fmaxf(v0.z, 0.f) + c1 * fmaxf(v1.z, 0.f);
        acc.w += c0 * fmaxf(v0.w, 0.f) + c1 * fmaxf(v1.w, 0.f);
    }
    if (e < s1) {
        int   r0 = __ldg(src + e);
        float c0 = __ldg(scl + e);
        float4 v0 = __ldg((const float4*)(x + (size_t)r0 * EMB) + lane);
        acc.x += c0 * fmaxf(v0.x, 0.f);
        acc.y += c0 * fmaxf(v0.y, 0.f);
        acc.z += c0 * fmaxf(v0.z, 0.f);
        acc.w += c0 * fmaxf(v0.w, 0.f);
    }

    size_t offn = (size_t)node * 32 + lane;
    float4 v = ((const float4*)x)[offn];
    float4 r = ((const float4*)root)[lane];
    float invd = 1.0f / __ldg(deg + node);
    float4 t;
    t.x = acc.x + fmaxf(v.x + r.x, 0.f) * invd;
    t.y = acc.y + fmaxf(v.y + r.y, 0.f) * invd;
    t.z = acc.z + fmaxf(v.z + r.z, 0.f) * invd;
    t.w = acc.w + fmaxf(v.w + r.w, 0.f) * invd;

    if (!END) {
        ((float4*)hout)[offn] = t;
        return;
    }

    float4 h = ((const float4*)h0)[offn];
    t.x += h.x; t.y += h.y; t.z += h.z; t.w += h.w;

    float s  = t.x + t.y + t.z + t.w;
    float ss = t.x * t.x + t.y * t.y + t.z * t.z + t.w * t.w;
#pragma unroll
    for (int o = 16; o; o >>= 1) {
        s  += __shfl_xor_sync(0xffffffffu, s, o);
        ss += __shfl_xor_sync(0xffffffffu, ss, o);
    }
    float mean = s * (1.0f / 128.0f);
    float var  = ss * (1.0f / 128.0f) - mean * mean;
    float rstd = rsqrtf(var + 1e-5f);
    float4 g = ((const float4*)lng)[lane];
    float4 b = ((const float4*)lnb)[lane];
    float4 y;
    y.x = (t.x - mean) * rstd * g.x + b.x;
    y.y = (t.y - mean) * rstd * g.y + b.y;
    y.z = (t.z - mean) * rstd * g.z + b.z;
    y.w = (t.w - mean) * rstd * g.w + b.w;
    y.x = (y.x > 0.f) ? y.x : 0.1f * y.x;
    y.y = (y.y > 0.f) ? y.y : 0.1f * y.y;
    y.z = (y.z > 0.f) ? y.z : 0.1f * y.z;
    y.w = (y.w > 0.f) ? y.w : 0.1f * y.w;
    ((float4*)hout)[offn] = y;
    if (node >= N_INST) {
        size_t oo = (size_t)(node - N_INST) * 128 + (size_t)(layer + 1) * 32 + lane;
        ((float4*)out)[oo] = y;
    }
}

// ---------------- write out[:, 0:128] = h0[net nodes] ----------------
__global__ void copy_out0_k(const float* __restrict__ h0, float* __restrict__ out)
{
    int idx = blockIdx.x * blockDim.x + threadIdx.x;
    if (idx >= N_NET * 32) return;
    int n = idx >> 5, q = idx & 31;
    ((float4*)out)[(size_t)n * 128 + q] =
        ((const float4*)h0)[(size_t)(N_INST + n) * 32 + q];
}

// ---------------- launch ----------------
extern "C" void kernel_launch(void* const* d_in, const int* in_sizes, int n_in,
                              void* d_out, int out_size)
{
    const float* x       = (const float*)d_in[0];
    const float* x_net   = (const float*)d_in[1];
    const int*   ei1     = (const int*)d_in[2];
    const int*   ei2     = (const int*)d_in[3];
    const float* enc1_W  = (const float*)d_in[5];
    const float* enc1_b  = (const float*)d_in[6];
    const float* enc2_W  = (const float*)d_in[7];
    const float* enc2_b  = (const float*)d_in[8];
    const float* encn1_W = (const float*)d_in[9];
    const float* encn1_b = (const float*)d_in[10];
    const float* encn2_W = (const float*)d_in[11];
    const float* encn2_b = (const float*)d_in[12];
    const float* conv_W  = (const float*)d_in[13];
    const float* conv_b  = (const float*)d_in[14];
    const float* conv_r  = (const float*)d_in[15];
    const float* rec_W   = (const float*)d_in[16];
    const float* rec_b   = (const float*)d_in[17];
    const float* rec_r   = (const float*)d_in[18];
    const float* ln_g    = (const float*)d_in[19];
    const float* ln_b    = (const float*)d_in[20];
    float* out = (float*)d_out;
    const int E = in_sizes[2] / 2;

    float *h0, *h, *hm, *xb, *sc, *deg1, *dinv1, *deg2, *dinv2;
    float *scl1, *scl2;
    int *cnt, *cur, *part, *off1, *off2, *src1, *src2;
    cudaGetSymbolAddress((void**)&h0,    g_h0);
    cudaGetSymbolAddress((void**)&h,     g_h);
    cudaGetSymbolAddress((void**)&hm,    g_hm);
    cudaGetSymbolAddress((void**)&xb,    g_x);
    cudaGetSymbolAddress((void**)&sc,    g_sc);
    cudaGetSymbolAddress((void**)&deg1,  g_deg1);
    cudaGetSymbolAddress((void**)&dinv1, g_dinv1);
    cudaGetSymbolAddress((void**)&deg2,  g_deg2);
    cudaGetSymbolAddress((void**)&dinv2, g_dinv2);
    cudaGetSymbolAddress((void**)&cnt,   g_cnt);
    cudaGetSymbolAddress((void**)&cur,   g_cur);
    cudaGetSymbolAddress((void**)&part,  g_part);
    cudaGetSymbolAddress((void**)&off1,  g_off1);
    cudaGetSymbolAddress((void**)&off2,  g_off2);
    cudaGetSymbolAddress((void**)&src1,  g_src1);
    cudaGetSymbolAddress((void**)&src2,  g_src2);
    cudaGetSymbolAddress((void**)&scl1,  g_scl1);
    cudaGetSymbolAddress((void**)&scl2,  g_scl2);

    dim3 blk(256);
    auto gg = [](int M, int N) { return dim3((unsigned)((M + 127) / 128), (unsigned)(N / 128)); };
    const int npart = (NTOT + 1023) >> 10;
    const int node_blocks = (NTOT + 255) / 256;
    const int edge_blocks = (E + 255) / 256;
    const int warp_blocks = (NTOT * 32 + 255) / 256;

    // encoders -> h0 (leaky at every linear)
    gemm_tc<true><<<gg(N_INST, 256), blk>>>(x,      enc1_W,  enc1_b,  sc,  N_INST, 256, 64);
    gemm_tc<true><<<gg(N_INST, 128), blk>>>(sc,     enc2_W,  enc2_b,  h0,  N_INST, 128, 256);
    gemm_tc<true><<<gg(N_NET, 128),  blk>>>(x_net,  encn1_W, encn1_b, sc,  N_NET,  128, 64);
    gemm_tc<true><<<gg(N_NET, 128),  blk>>>(sc,     encn2_W, encn2_b, h0 + (size_t)N_INST * EMB,
                                            N_NET, 128, 128);
    copy_out0_k<<<(N_NET * 32 + 255) / 256, blk>>>(h0, out);

    // degrees
    fill1_k<<<node_blocks, blk>>>(deg1, NTOT);
    fill1_k<<<node_blocks, blk>>>(deg2, NTOT);
    deg_count_k<<<edge_blocks, blk>>>(ei1, deg1, E);
    deg_count_k<<<edge_blocks, blk>>>(ei2, deg2, E);
    dinv_k<<<node_blocks, blk>>>(deg1, dinv1, NTOT);
    dinv_k<<<node_blocks, blk>>>(deg2, dinv2, NTOT);

    // CSR build, edge set 1
    cudaMemsetAsync(cnt, 0, NTOT * sizeof(int), 0);
    hist_k<<<edge_blocks, blk>>>(ei1 + E, cnt, E);
    scan1_k<<<npart, blk>>>(cnt, part, NTOT);
    scan2_k<<<1, 512>>>(part, npart);
    scan3_k<<<npart, blk>>>(cnt, part, off1, cur, NTOT);
    csr_fill_k<<<edge_blocks, blk>>>(ei1, ei1 + E, dinv1, cur, src1, scl1, E);

    // CSR build, edge set 2
    cudaMemsetAsync(cnt, 0, NTOT * sizeof(int), 0);
    hist_k<<<edge_blocks, blk>>>(ei2 + E, cnt, E);
    scan1_k<<<npart, blk>>>(cnt, part, NTOT);
    scan2_k<<<1, 512>>>(part, npart);
    scan3_k<<<npart, blk>>>(cnt, part, off2, cur, NTOT);
    csr_fill_k<<<edge_blocks, blk>>>(ei2, ei2 + E, dinv2, cur, src2, scl2, E);

    const float* hin = h0;
    for (int l = 0; l < 3; l++) {
        gemm_tc<false><<<gg(NTOT, 128), blk>>>(hin, conv_W + (size_t)l * EMB * EMB,
                                               conv_b + l * EMB, xb, NTOT, 128, 128);
        conv_gather_k<false><<<warp_blocks, blk>>>(off1, src1, scl1, xb,
                                                   conv_r + l * EMB, deg1,
                                                   nullptr, nullptr, nullptr,
                                                   hm, nullptr, l);
        gemm_tc<false><<<gg(NTOT, 128), blk>>>(hm, rec_W + (size_t)l * EMB * EMB,
                                               rec_b + l * EMB, xb, NTOT, 128, 128);
        conv_gather_k<true><<<warp_blocks, blk>>>(off2, src2, scl2, xb,
                                                  rec_r + l * EMB, deg2,
                                                  h0, ln_g + l * EMB, ln_b + l * EMB,
                                                  h, out, l);
        hin = h;
    }
}